// round 4
// baseline (speedup 1.0000x reference)
#include <cuda_runtime.h>

// SpecEMA single-pass decoupled-lookback scan.
// x held in REGISTERS between aggregate phase and replay phase:
// exactly one DRAM read of x, one write of y. No smem staging.
#define BB 64
#define CC 2
#define TT 4000
#define FF 96
#define NF4 24              // FF/4
#define NSUB 8
#define LS 4
#define LCH (NSUB * LS)     // 32
#define NCH (TT / LCH)      // 125
#define NTHR (NSUB * NF4)   // 192

#define ALPHA_F 0.99f
#define OMA_F ((float)(1.0 - 0.99))   // float32(1 - 0.99), matches jax

__host__ __device__ constexpr float fpow(float a, int n) {
    float r = 1.0f;
    for (int i = 0; i < n; i++) r *= a;
    return r;
}

// ---- scratch (__device__ globals; allocation-free rule) ----
__device__ float4 g_agg[BB * NCH * NF4];
__device__ float4 g_inc[BB * NCH * NF4];
__device__ int    g_flag[BB * NCH];      // 0=empty 1=agg 2=inclusive
__device__ unsigned g_ctr;

__device__ __forceinline__ int ld_acquire(const int* p) {
    int v;
    asm volatile("ld.global.acquire.gpu.b32 %0, [%1];" : "=r"(v) : "l"(p));
    return v;
}
__device__ __forceinline__ void st_release(int* p, int v) {
    asm volatile("st.global.release.gpu.b32 [%0], %1;" :: "l"(p), "r"(v));
}

#define EMA4(s, a, c)                                                        \
    (s).x = fmaf(fmaf((a).x, (a).x, (c).x * (c).x), OMA_F, (s).x * ALPHA_F); \
    (s).y = fmaf(fmaf((a).y, (a).y, (c).y * (c).y), OMA_F, (s).y * ALPHA_F); \
    (s).z = fmaf(fmaf((a).z, (a).z, (c).z * (c).z), OMA_F, (s).z * ALPHA_F); \
    (s).w = fmaf(fmaf((a).w, (a).w, (c).w * (c).w), OMA_F, (s).w * ALPHA_F)

#define FMA4(acc, w, v)                  \
    (acc).x = fmaf((w), (v).x, (acc).x); \
    (acc).y = fmaf((w), (v).y, (acc).y); \
    (acc).z = fmaf((w), (v).z, (acc).z); \
    (acc).w = fmaf((w), (v).w, (acc).w)

// fold: s = aLS * s + P   (advance state across one sub-chunk)
#define FOLD4(s, aLS, P)                 \
    (s).x = fmaf((aLS), (s).x, (P).x);   \
    (s).y = fmaf((aLS), (s).y, (P).y);   \
    (s).z = fmaf((aLS), (s).z, (P).z);   \
    (s).w = fmaf((aLS), (s).w, (P).w)

// ---------------- reset (graph replays reuse globals) ----------------
__global__ void k_reset() {
    int i = blockIdx.x * blockDim.x + threadIdx.x;
    if (i < BB * NCH) g_flag[i] = 0;
    if (i == 0) g_ctr = 0u;
}

// ---------------- single-pass scan ----------------
__global__ void __launch_bounds__(NTHR) k_scan(const float* __restrict__ x,
                                               const float* __restrict__ state,
                                               float* __restrict__ out,
                                               float* __restrict__ fstate,
                                               int write_state) {
    __shared__ float4 sP[NSUB][NF4];
    __shared__ unsigned s_vbid;

    const int tid = threadIdx.x;
    if (tid == 0) s_vbid = atomicAdd(&g_ctr, 1u);
    __syncthreads();
    const int vbid = (int)s_vbid;
    const int b   = vbid % BB;        // b fastest: predecessors scheduled first
    const int j   = vbid / BB;
    const int f4  = tid % NF4;
    const int sub = tid / NF4;

    const float aLS = fpow(ALPHA_F, LS);    // alpha^4
    const float aB  = fpow(ALPHA_F, LCH);   // alpha^32

    const size_t e0 = (((size_t)b * CC + 0) * TT + (size_t)j * LCH + sub * LS) * FF + f4 * 4;
    const size_t e1 = (((size_t)b * CC + 1) * TT + (size_t)j * LCH + sub * LS) * FF + f4 * 4;
    const float4* p0 = (const float4*)(x + e0);   // row stride = NF4 float4
    const float4* p1 = (const float4*)(x + e1);

    // ---- phase 1: load sub-chunk into REGISTERS, partial EMA from s=0 ----
    float4 xa[LS], xc[LS];
    float4 P = make_float4(0.f, 0.f, 0.f, 0.f);
#pragma unroll
    for (int t = 0; t < LS; t++) {
        xa[t] = __ldcs(p0 + t * NF4);   // streaming: x read exactly once
        xc[t] = __ldcs(p1 + t * NF4);
        EMA4(P, xa[t], xc[t]);
    }
    sP[sub][f4] = P;
    __syncthreads();

    // block aggregate (every thread folds the 8 partials)
    float4 A = sP[0][f4];
#pragma unroll
    for (int k = 1; k < NSUB; k++) {
        float4 t4 = sP[k][f4];
        FOLD4(A, aLS, t4);
    }

    const int chain = b * NCH + j;
    if (sub == 0) {                     // tids 0..23 (all in warp 0)
        g_agg[chain * NF4 + f4] = A;
        __syncwarp(0x00FFFFFFu);
        if (tid == 0) { __threadfence(); st_release(&g_flag[chain], 1); }
    }

    // ---- phase 2: barrier-free lookback (every thread independently) ----
    float4 S;
    if (j == 0) {
        S = *(const float4*)(state + f4 * 4);
    } else {
        float4 acc = make_float4(0.f, 0.f, 0.f, 0.f);
        float w = 1.0f;
        int k = j - 1;
        for (;;) {
            const int* fl = &g_flag[b * NCH + k];
            int st = ld_acquire(fl);
            int spins = 0;
            while (st == 0) {
                if (++spins > 8) { __nanosleep(128); spins = 0; }
                st = ld_acquire(fl);
            }
            if (st == 2) {
                float4 v = g_inc[(b * NCH + k) * NF4 + f4];
                FMA4(acc, w, v);
                break;
            }
            float4 v = g_agg[(b * NCH + k) * NF4 + f4];
            FMA4(acc, w, v);
            w *= aB;
            if (k == 0) {
                float4 s0 = *(const float4*)(state + f4 * 4);
                FMA4(acc, w, s0);
                break;
            }
            k--;
        }
        S = acc;
    }

    // ---- publish inclusive ASAP (unblocks successors before our stores) ----
    if (sub == 0) {
        float4 inc = A;
        inc.x = fmaf(aB, S.x, A.x);
        inc.y = fmaf(aB, S.y, A.y);
        inc.z = fmaf(aB, S.z, A.z);
        inc.w = fmaf(aB, S.w, A.w);
        g_inc[chain * NF4 + f4] = inc;
        __syncwarp(0x00FFFFFFu);
        if (tid == 0) { __threadfence(); st_release(&g_flag[chain], 2); }
    }

    // ---- start state for this sub-chunk ----
    float4 s4 = S;
#pragma unroll
    for (int k = 0; k < NSUB - 1; k++) {     // bounded unroll; predicated on k<sub
        if (k < sub) {
            float4 Pk = sP[k][f4];
            FOLD4(s4, aLS, Pk);
        }
    }

    // ---- phase 3: replay from REGISTERS, write outputs (streaming) ----
    float4* o0 = (float4*)(out + e0);
    float4* o1 = (float4*)(out + e1);
#pragma unroll
    for (int t = 0; t < LS; t++) {
        EMA4(s4, xa[t], xc[t]);
        float4 r;
        r.x = rsqrtf(s4.x); r.y = rsqrtf(s4.y);
        r.z = rsqrtf(s4.z); r.w = rsqrtf(s4.w);
        float4 y0, y1;
        y0.x = xa[t].x * r.x; y0.y = xa[t].y * r.y;
        y0.z = xa[t].z * r.z; y0.w = xa[t].w * r.w;
        y1.x = xc[t].x * r.x; y1.y = xc[t].y * r.y;
        y1.z = xc[t].z * r.z; y1.w = xc[t].w * r.w;
        __stcs(o0 + t * NF4, y0);
        __stcs(o1 + t * NF4, y1);
    }

    if (write_state && j == NCH - 1 && sub == NSUB - 1) {
        *(float4*)(fstate + b * FF + f4 * 4) = s4;
    }
}

extern "C" void kernel_launch(void* const* d_in, const int* in_sizes, int n_in,
                              void* d_out, int out_size) {
    const float* feat  = (const float*)d_in[0];   // [B,C,T,F] f32
    const float* state = (const float*)d_in[1];   // [1,1,F]   f32
    float* out = (float*)d_out;

    const int n_out_main = BB * CC * TT * FF;     // 49,152,000
    int write_state = (out_size >= n_out_main + BB * FF) ? 1 : 0;
    float* fstate = out + n_out_main;

    k_reset<<<(BB * NCH + 255) / 256, 256>>>();
    k_scan<<<BB * NCH, NTHR>>>(feat, state, out, fstate, write_state);
}

// round 5
// speedup vs baseline: 1.1168x; 1.1168x over previous
#include <cuda_runtime.h>

// SpecEMA single-pass decoupled-lookback scan.
// x staged in SMEM (read once from DRAM), float4 throughout, generation-coded
// flags (no reset kernel). s_t = (1-a)|x_t|^2 + a*s_{t-1}; y_t = x_t*rsqrt(s_t).
#define BB 64
#define CC 2
#define TT 4000
#define FF 96
#define NF4 24               // FF/4
#define NSUB 8
#define LS 5
#define LCH (NSUB * LS)      // 40
#define NCH (TT / LCH)       // 100
#define NTHR (NSUB * NF4)    // 192
#define GRID (BB * NCH)      // 6400

#define ALPHA_F 0.99f
#define OMA_F ((float)(1.0 - 0.99))   // float32(1 - 0.99), matches jax

__host__ __device__ constexpr float fpow(float a, int n) {
    float r = 1.0f;
    for (int i = 0; i < n; i++) r *= a;
    return r;
}

// ---- scratch (__device__ globals; allocation-free rule; zero-initialized) ----
__device__ float4 g_agg[GRID * NF4];
__device__ float4 g_inc[GRID * NF4];
__device__ unsigned g_flag[GRID];    // gen-coded: 2*gen+1 = agg, 2*gen+2 = inclusive
__device__ unsigned g_ctr;           // monotone across launches (generation trick)

__device__ __forceinline__ unsigned ld_acquire(const unsigned* p) {
    unsigned v;
    asm volatile("ld.global.acquire.gpu.b32 %0, [%1];" : "=r"(v) : "l"(p));
    return v;
}
__device__ __forceinline__ void st_release(unsigned* p, unsigned v) {
    asm volatile("st.global.release.gpu.b32 [%0], %1;" :: "l"(p), "r"(v));
}

#define EMA4(s, a, c)                                                        \
    (s).x = fmaf(fmaf((a).x, (a).x, (c).x * (c).x), OMA_F, (s).x * ALPHA_F); \
    (s).y = fmaf(fmaf((a).y, (a).y, (c).y * (c).y), OMA_F, (s).y * ALPHA_F); \
    (s).z = fmaf(fmaf((a).z, (a).z, (c).z * (c).z), OMA_F, (s).z * ALPHA_F); \
    (s).w = fmaf(fmaf((a).w, (a).w, (c).w * (c).w), OMA_F, (s).w * ALPHA_F)

#define FMA4(acc, w, v)                  \
    (acc).x = fmaf((w), (v).x, (acc).x); \
    (acc).y = fmaf((w), (v).y, (acc).y); \
    (acc).z = fmaf((w), (v).z, (acc).z); \
    (acc).w = fmaf((w), (v).w, (acc).w)

// s = aLS * s + P
#define FOLD4(s, aLS, P)                 \
    (s).x = fmaf((aLS), (s).x, (P).x);   \
    (s).y = fmaf((aLS), (s).y, (P).y);   \
    (s).z = fmaf((aLS), (s).z, (P).z);   \
    (s).w = fmaf((aLS), (s).w, (P).w)

__global__ void __launch_bounds__(NTHR, 6)
k_scan(const float* __restrict__ x,
       const float* __restrict__ state,
       float* __restrict__ out,
       float* __restrict__ fstate,
       int write_state) {
    __shared__ float4 xs[LCH][CC][NF4];   // 30720 B
    __shared__ float4 sP[NSUB][NF4];      //  3072 B
    __shared__ unsigned s_vbid;

    const int tid = threadIdx.x;
    if (tid == 0) s_vbid = atomicAdd(&g_ctr, 1u);
    __syncthreads();
    const unsigned raw = s_vbid;
    const unsigned gen = raw / (unsigned)GRID;
    const int vbid = (int)(raw % (unsigned)GRID);
    const unsigned V_AGG = 2u * gen + 1u;     // this launch's flag values
    const unsigned V_INC = 2u * gen + 2u;

    const int b   = vbid % BB;        // b fastest: predecessors scheduled first
    const int j   = vbid / BB;
    const int f4  = tid % NF4;
    const int sub = tid / NF4;

    const float aLS = fpow(ALPHA_F, LS);    // alpha^5
    const float aB  = fpow(ALPHA_F, LCH);   // alpha^40

    const size_t e0 = (((size_t)b * CC + 0) * TT + (size_t)j * LCH + sub * LS) * FF + f4 * 4;
    const size_t e1 = (((size_t)b * CC + 1) * TT + (size_t)j * LCH + sub * LS) * FF + f4 * 4;
    const float4* p0 = (const float4*)(x + e0);   // time stride = NF4 float4
    const float4* p1 = (const float4*)(x + e1);

    // ---- phase 1: stream x chunk into SMEM, per-sub partial EMA from s=0 ----
    float4 P = make_float4(0.f, 0.f, 0.f, 0.f);
#pragma unroll
    for (int t = 0; t < LS; t++) {
        float4 a = __ldcs(p0 + t * NF4);    // streaming: x read exactly once
        float4 c = __ldcs(p1 + t * NF4);
        xs[sub * LS + t][0][f4] = a;
        xs[sub * LS + t][1][f4] = c;
        EMA4(P, a, c);
    }
    sP[sub][f4] = P;
    __syncthreads();

    // block aggregate (cheap; every thread folds all partials)
    float4 A = sP[0][f4];
#pragma unroll
    for (int k = 1; k < NSUB; k++) {
        float4 t4 = sP[k][f4];
        FOLD4(A, aLS, t4);
    }

    const int chain = b * NCH + j;
    if (sub == 0) {                     // tids 0..23, all in warp 0
        g_agg[chain * NF4 + f4] = A;
        __syncwarp(0x00FFFFFFu);
        if (tid == 0) { __threadfence(); st_release(&g_flag[chain], V_AGG); }
    }

    // ---- phase 2: barrier-free lookback (every thread independently) ----
    float4 S;
    if (j == 0) {
        S = *(const float4*)(state + f4 * 4);
    } else {
        float4 acc = make_float4(0.f, 0.f, 0.f, 0.f);
        float w = 1.0f;
        int k = j - 1;
        for (;;) {
            const unsigned* fl = &g_flag[b * NCH + k];
            unsigned st = ld_acquire(fl);
            int spins = 0;
            while (st < V_AGG) {                 // stale generation == empty
                if (++spins > 8) { __nanosleep(128); spins = 0; }
                st = ld_acquire(fl);
            }
            if (st == V_INC) {
                float4 v = g_inc[(b * NCH + k) * NF4 + f4];
                FMA4(acc, w, v);
                break;
            }
            float4 v = g_agg[(b * NCH + k) * NF4 + f4];
            FMA4(acc, w, v);
            w *= aB;
            if (k == 0) {
                float4 s0 = *(const float4*)(state + f4 * 4);
                FMA4(acc, w, s0);
                break;
            }
            k--;
        }
        S = acc;
    }

    // ---- publish inclusive ASAP (unblocks successors before our stores) ----
    if (sub == 0) {
        float4 inc;
        inc.x = fmaf(aB, S.x, A.x);
        inc.y = fmaf(aB, S.y, A.y);
        inc.z = fmaf(aB, S.z, A.z);
        inc.w = fmaf(aB, S.w, A.w);
        g_inc[chain * NF4 + f4] = inc;
        __syncwarp(0x00FFFFFFu);
        if (tid == 0) { __threadfence(); st_release(&g_flag[chain], V_INC); }
    }

    // ---- start state for this thread's sub-chunk ----
    float4 s4 = S;
#pragma unroll
    for (int k = 0; k < NSUB - 1; k++) {
        if (k < sub) {
            float4 Pk = sP[k][f4];
            FOLD4(s4, aLS, Pk);
        }
    }

    // ---- phase 3: replay from SMEM, write outputs (streaming stores) ----
    float4* o0 = (float4*)(out + e0);
    float4* o1 = (float4*)(out + e1);
#pragma unroll
    for (int t = 0; t < LS; t++) {
        float4 a = xs[sub * LS + t][0][f4];
        float4 c = xs[sub * LS + t][1][f4];
        EMA4(s4, a, c);
        float4 r;
        r.x = rsqrtf(s4.x); r.y = rsqrtf(s4.y);
        r.z = rsqrtf(s4.z); r.w = rsqrtf(s4.w);
        float4 y0, y1;
        y0.x = a.x * r.x; y0.y = a.y * r.y; y0.z = a.z * r.z; y0.w = a.w * r.w;
        y1.x = c.x * r.x; y1.y = c.y * r.y; y1.z = c.z * r.z; y1.w = c.w * r.w;
        __stcs(o0 + t * NF4, y0);
        __stcs(o1 + t * NF4, y1);
    }

    if (write_state && j == NCH - 1 && sub == NSUB - 1) {
        *(float4*)(fstate + b * FF + f4 * 4) = s4;
    }
}

extern "C" void kernel_launch(void* const* d_in, const int* in_sizes, int n_in,
                              void* d_out, int out_size) {
    const float* feat  = (const float*)d_in[0];   // [B,C,T,F] f32
    const float* state = (const float*)d_in[1];   // [1,1,F]   f32
    float* out = (float*)d_out;

    const int n_out_main = BB * CC * TT * FF;     // 49,152,000
    int write_state = (out_size >= n_out_main + BB * FF) ? 1 : 0;
    float* fstate = out + n_out_main;

    k_scan<<<GRID, NTHR>>>(feat, state, out, fstate, write_state);
}